// round 7
// baseline (speedup 1.0000x reference)
#include <cuda_runtime.h>
#include <cuda_fp16.h>
#include <cstdint>

#define BB 4
#define CH 1024
#define HH 50
#define WW 50
#define KK 512
#define NPIX (HH*WW)              // 2500
#define GPTS 8

// NHWC-transposed features in fp16: [B][H][W][C]  (20.5 MB scratch)
__device__ __align__(16) __half FT[BB * HH * WW * CH];

// ---------------------------------------------------------------------------
// Kernel 1: NCHW fp32 -> NHWC fp16 transpose-convert (measured ~12us)
// ---------------------------------------------------------------------------
__global__ __launch_bounds__(256)
void transpose_kernel(const float* __restrict__ f) {
    __shared__ __align__(16) float tile[32][133];
    const int b  = blockIdx.z;
    const int p0 = blockIdx.x * 128;
    const int c0 = blockIdx.y * 32;
    const int t  = threadIdx.x;

    const float* fb = f + (size_t)b * CH * NPIX + (size_t)c0 * NPIX;
    #pragma unroll
    for (int j = 0; j < 4; j++) {
        int idx = t + j * 256;
        int c = idx >> 5;
        int q = idx & 31;
        int p = p0 + 4 * q;
        float4 v = make_float4(0.f, 0.f, 0.f, 0.f);
        if (p < NPIX) v = *(const float4*)(fb + (size_t)c * NPIX + p);
        tile[c][4 * q + 0] = v.x;
        tile[c][4 * q + 1] = v.y;
        tile[c][4 * q + 2] = v.z;
        tile[c][4 * q + 3] = v.w;
    }
    __syncthreads();

    __half* ob = FT + (size_t)b * NPIX * CH + c0;
    #pragma unroll
    for (int j = 0; j < 2; j++) {
        int idx = t + j * 256;
        int p = idx >> 2;
        int g = idx & 3;
        if (p0 + p < NPIX) {
            __half2 h0 = __floats2half2_rn(tile[8*g + 0][p], tile[8*g + 1][p]);
            __half2 h1 = __floats2half2_rn(tile[8*g + 2][p], tile[8*g + 3][p]);
            __half2 h2 = __floats2half2_rn(tile[8*g + 4][p], tile[8*g + 5][p]);
            __half2 h3 = __floats2half2_rn(tile[8*g + 6][p], tile[8*g + 7][p]);
            uint4 v;
            v.x = *(const unsigned int*)&h0;
            v.y = *(const unsigned int*)&h1;
            v.z = *(const unsigned int*)&h2;
            v.w = *(const unsigned int*)&h3;
            *(uint4*)(ob + (size_t)(p0 + p) * CH + 8 * g) = v;
        }
    }
}

// ---------------------------------------------------------------------------
// Kernel 2: fused RoIAlign + 2x2 avg pool.
// Grid (K, 4): 256 channels per block. 64 threads, 4 ch/thread, LDG.64 taps.
// Row-streaming accumulator (float4 prev/cur rowsums), two phases:
//   phase A: grid rows 0-4 -> pooled rows 0-3, stage fp32, drain
//   phase B: grid rows 4-7 -> pooled rows 4-6, stage fp32, drain
// ---------------------------------------------------------------------------
#define SB_STRIDE 260     // floats per staging row (16B-aligned, mild bank shift)

__device__ __forceinline__ void fma4(float4& a, uint2 u, float w) {
    float2 f0 = __half22float2(*(const __half2*)&u.x);
    float2 f1 = __half22float2(*(const __half2*)&u.y);
    a.x += f0.x * w;  a.y += f0.y * w;
    a.z += f1.x * w;  a.w += f1.y * w;
}

template<int GY0, int NP>   // NP pooled rows from grid rows GY0..GY0+NP
__device__ __forceinline__
void roi_phase(const __half* __restrict__ bptr, float* __restrict__ outk,
               int tid, float* sbuf, const float (*s_w)[GPTS][4],
               const int* s_x0, const int* s_y0) {
    float4 prev[7];
    #pragma unroll
    for (int g = 0; g <= NP; g++) {
        const int gy = GY0 + g;
        const __half* rp = bptr + (size_t)s_y0[gy] * (WW * CH);
        float4 rh[7];
        float4 cprev;
        #pragma unroll
        for (int gx = 0; gx < GPTS; gx++) {
            const float4 w = *(const float4*)&s_w[gy][gx][0];
            const __half* p = rp + s_x0[gx] * CH;
            uint2 u00 = *(const uint2*)(p);
            uint2 u01 = *(const uint2*)(p + CH);
            uint2 u10 = *(const uint2*)(p + WW * CH);
            uint2 u11 = *(const uint2*)(p + WW * CH + CH);

            float4 cur = make_float4(0.f, 0.f, 0.f, 0.f);
            fma4(cur, u00, w.x);
            fma4(cur, u01, w.y);
            fma4(cur, u10, w.z);
            fma4(cur, u11, w.w);

            if (gx > 0) {
                rh[gx-1].x = cprev.x + cur.x;
                rh[gx-1].y = cprev.y + cur.y;
                rh[gx-1].z = cprev.z + cur.z;
                rh[gx-1].w = cprev.w + cur.w;
            }
            cprev = cur;
        }
        if (g > 0) {
            // stage pooled row (GY0+g-1), phase-local row r = g-1
            const int r = g - 1;
            #pragma unroll
            for (int px = 0; px < 7; px++) {
                float4 o;
                o.x = prev[px].x + rh[px].x;
                o.y = prev[px].y + rh[px].y;
                o.z = prev[px].z + rh[px].z;
                o.w = prev[px].w + rh[px].w;
                *(float4*)&sbuf[(r * 7 + px) * SB_STRIDE + tid * 4] = o;
            }
        }
        #pragma unroll
        for (int px = 0; px < 7; px++) prev[px] = rh[px];
    }
    __syncthreads();

    // drain: 256 channels x NP*7 px, mostly-coalesced runs of NP*7 floats
    constexpr int PXN = NP * 7;
    constexpr int N   = PXN * 256;
    float* ob = outk + GY0 * 7;
    #pragma unroll 8
    for (int i = tid; i < N; i += 64) {
        int c   = i / PXN;          // compile-time divisor
        int rem = i - c * PXN;
        ob[c * 49 + rem] = sbuf[rem * SB_STRIDE + c];
    }
    __syncthreads();
}

__global__ __launch_bounds__(64, 7)
void roi_pool_kernel(const float* __restrict__ rois, float* __restrict__ out) {
    const int k     = blockIdx.x;
    const int cblk  = blockIdx.y;          // 0..3: 256-channel slice
    const int tid   = threadIdx.x;

    __shared__ __align__(16) float sbuf[28 * SB_STRIDE];   // 29.1 KB staging
    __shared__ __align__(16) float s_w[GPTS][GPTS][4];     // folded weights
    __shared__ float s_wx[GPTS], s_wy[GPTS], s_vx[GPTS], s_vy[GPTS];
    __shared__ int   s_x0[GPTS], s_y0[GPTS];
    __shared__ int   s_b;

    if (tid < GPTS) {
        float x1 = __ldg(&rois[k * 5 + 1]) * 0.0625f;
        float y1 = __ldg(&rois[k * 5 + 2]) * 0.0625f;
        float x2 = __ldg(&rois[k * 5 + 3]) * 0.0625f;
        float y2 = __ldg(&rois[k * 5 + 4]) * 0.0625f;
        float bh = fmaxf(y2 - y1, 0.0f) * (1.0f / 7.0f);
        float bw = fmaxf(x2 - x1, 0.0f) * (1.0f / 7.0f);
        float xv = x1 + (float)tid * bw;
        float yv = y1 + (float)tid * bh;
        s_vx[tid] = (xv >= 0.0f && xv < (float)WW) ? 1.0f : 0.0f;
        s_vy[tid] = (yv >= 0.0f && yv < (float)HH) ? 1.0f : 0.0f;
        int x0 = (int)floorf(xv);  x0 = min(max(x0, 0), WW - 2);
        int y0 = (int)floorf(yv);  y0 = min(max(y0, 0), HH - 2);
        s_x0[tid] = x0;  s_y0[tid] = y0;
        s_wx[tid] = xv - (float)x0;
        s_wy[tid] = yv - (float)y0;
        if (tid == 0) s_b = (int)__ldg(&rois[k * 5 + 0]);
    }
    __syncthreads();

    // folded bilinear weights incl. 0.25 pool factor and valid mask
    {
        int gy = tid >> 3, gx = tid & 7;   // 64 threads = all (gy,gx)
        float wy = s_wy[gy], wx = s_wx[gx];
        float sc = 0.25f * s_vy[gy] * s_vx[gx];
        s_w[gy][gx][0] = (1.0f - wy) * (1.0f - wx) * sc;
        s_w[gy][gx][1] = (1.0f - wy) * wx * sc;
        s_w[gy][gx][2] = wy * (1.0f - wx) * sc;
        s_w[gy][gx][3] = wy * wx * sc;
    }
    __syncthreads();

    const int c0 = cblk * 256 + tid * 4;
    const __half* bptr = FT + (size_t)s_b * (NPIX * CH) + c0;
    float* outk = out + (size_t)k * (CH * 49) + (size_t)(cblk * 256) * 49;

    roi_phase<0, 4>(bptr, outk, tid, sbuf, s_w, s_x0, s_y0);   // pooled rows 0-3
    roi_phase<4, 3>(bptr, outk, tid, sbuf, s_w, s_x0, s_y0);   // pooled rows 4-6
}

// ---------------------------------------------------------------------------
extern "C" void kernel_launch(void* const* d_in, const int* in_sizes, int n_in,
                              void* d_out, int out_size) {
    const float* features = (const float*)d_in[0];
    const float* rois     = (const float*)d_in[1];
    float* out            = (float*)d_out;

    dim3 tgrid((NPIX + 127) / 128, CH / 32, BB);   // (20, 32, 4)
    transpose_kernel<<<tgrid, 256>>>(features);
    roi_pool_kernel<<<dim3(KK, 4), 64>>>(rois, out);
}

// round 8
// speedup vs baseline: 1.0825x; 1.0825x over previous
#include <cuda_runtime.h>
#include <cuda_fp16.h>
#include <cstdint>

#define BB 4
#define CH 1024
#define HH 50
#define WW 50
#define KK 512
#define NPIX (HH*WW)              // 2500
#define GPTS 8

// NHWC-transposed features in fp16: [B][H][W][C]  (20.5 MB scratch)
__device__ __align__(16) __half FT[BB * HH * WW * CH];

// ---------------------------------------------------------------------------
// Kernel 1: NCHW fp32 -> NHWC fp16 transpose-convert (measured ~12us)
// ---------------------------------------------------------------------------
__global__ __launch_bounds__(256)
void transpose_kernel(const float* __restrict__ f) {
    __shared__ __align__(16) float tile[32][133];
    const int b  = blockIdx.z;
    const int p0 = blockIdx.x * 128;
    const int c0 = blockIdx.y * 32;
    const int t  = threadIdx.x;

    const float* fb = f + (size_t)b * CH * NPIX + (size_t)c0 * NPIX;
    #pragma unroll
    for (int j = 0; j < 4; j++) {
        int idx = t + j * 256;
        int c = idx >> 5;
        int q = idx & 31;
        int p = p0 + 4 * q;
        float4 v = make_float4(0.f, 0.f, 0.f, 0.f);
        if (p < NPIX) v = *(const float4*)(fb + (size_t)c * NPIX + p);
        tile[c][4 * q + 0] = v.x;
        tile[c][4 * q + 1] = v.y;
        tile[c][4 * q + 2] = v.z;
        tile[c][4 * q + 3] = v.w;
    }
    __syncthreads();

    __half* ob = FT + (size_t)b * NPIX * CH + c0;
    #pragma unroll
    for (int j = 0; j < 2; j++) {
        int idx = t + j * 256;
        int p = idx >> 2;
        int g = idx & 3;
        if (p0 + p < NPIX) {
            __half2 h0 = __floats2half2_rn(tile[8*g + 0][p], tile[8*g + 1][p]);
            __half2 h1 = __floats2half2_rn(tile[8*g + 2][p], tile[8*g + 3][p]);
            __half2 h2 = __floats2half2_rn(tile[8*g + 4][p], tile[8*g + 5][p]);
            __half2 h3 = __floats2half2_rn(tile[8*g + 6][p], tile[8*g + 7][p]);
            uint4 v;
            v.x = *(const unsigned int*)&h0;
            v.y = *(const unsigned int*)&h1;
            v.z = *(const unsigned int*)&h2;
            v.w = *(const unsigned int*)&h3;
            *(uint4*)(ob + (size_t)(p0 + p) * CH + 8 * g) = v;
        }
    }
}

// ---------------------------------------------------------------------------
// Kernel 2: fused RoIAlign + 2x2 avg pool.
// Grid (K, 2): 512 channels per CTA, 256 threads, 2 ch/thread (half2 taps).
// Row-streaming rowsums in registers (~65 regs); each completed pooled row
// goes straight to a dynamic-smem staging tile [512ch][<=28px] (stride 29),
// drained per phase with sequential scalar stores (28/21-float runs, L2
// merges the two phases of each 196B channel run).
//   phase A: grid rows 0-4 -> pooled rows 0-3
//   phase B: grid rows 4-7 -> pooled rows 4-6
// 3 CTAs/SM (24 warps) via 85-reg cap + 64KB smem.
// ---------------------------------------------------------------------------
#define SSTR 29   // smem channel stride (floats); 29 -> low-conflict both phases

extern __shared__ float sbuf[];   // 512 * SSTR floats = 59392 B

template<int GY0, int NP>         // NP pooled rows from grid rows GY0..GY0+NP
__device__ __forceinline__
void roi_phase(const __half* __restrict__ bptr, float* __restrict__ outk,
               int tid, const float (*s_w)[GPTS][4],
               const int* s_x0, const int* s_y0) {
    constexpr int PXN = NP * 7;
    const int c0 = tid * 2;

    float2 prev[7];
    #pragma unroll
    for (int g = 0; g <= NP; g++) {
        const int gy = GY0 + g;
        const __half* rp = bptr + (size_t)s_y0[gy] * (WW * CH);
        float2 rh[7];
        float2 cprev;
        #pragma unroll
        for (int gx = 0; gx < GPTS; gx++) {
            const float4 w = *(const float4*)&s_w[gy][gx][0];
            const __half* p = rp + s_x0[gx] * CH;
            float2 f00 = __half22float2(*(const __half2*)(p));
            float2 f01 = __half22float2(*(const __half2*)(p + CH));
            float2 f10 = __half22float2(*(const __half2*)(p + WW * CH));
            float2 f11 = __half22float2(*(const __half2*)(p + WW * CH + CH));

            float2 cur;
            cur.x = f00.x*w.x + f01.x*w.y + f10.x*w.z + f11.x*w.w;
            cur.y = f00.y*w.x + f01.y*w.y + f10.y*w.z + f11.y*w.w;

            if (gx > 0) {
                rh[gx-1].x = cprev.x + cur.x;
                rh[gx-1].y = cprev.y + cur.y;
            }
            cprev = cur;
        }
        if (g > 0) {
            const int r = g - 1;              // phase-local pooled row
            #pragma unroll
            for (int px = 0; px < 7; px++) {
                float ox = prev[px].x + rh[px].x;
                float oy = prev[px].y + rh[px].y;
                sbuf[(c0    ) * SSTR + r * 7 + px] = ox;
                sbuf[(c0 + 1) * SSTR + r * 7 + px] = oy;
            }
        }
        #pragma unroll
        for (int px = 0; px < 7; px++) prev[px] = rh[px];
    }
    __syncthreads();

    // drain: 512 channels x PXN px. Sequential i -> runs of PXN consecutive
    // floats per channel (stride 49 in out).
    constexpr int N = 512 * PXN;
    float* ob = outk + GY0 * 7;
    #pragma unroll 8
    for (int i = tid; i < N; i += 256) {
        int c   = i / PXN;                    // compile-time magic division
        int rem = i - c * PXN;
        ob[c * 49 + rem] = sbuf[c * SSTR + rem];
    }
    __syncthreads();
}

__global__ __launch_bounds__(256, 3)
void roi_pool_kernel(const float* __restrict__ rois, float* __restrict__ out) {
    const int k     = blockIdx.x;
    const int chunk = blockIdx.y;             // 0/1: channel half
    const int tid   = threadIdx.x;

    __shared__ __align__(16) float s_w[GPTS][GPTS][4];   // folded weights
    __shared__ float s_wx[GPTS], s_wy[GPTS], s_vx[GPTS], s_vy[GPTS];
    __shared__ int   s_x0[GPTS], s_y0[GPTS];
    __shared__ int   s_b;

    if (tid < GPTS) {
        float x1 = __ldg(&rois[k * 5 + 1]) * 0.0625f;
        float y1 = __ldg(&rois[k * 5 + 2]) * 0.0625f;
        float x2 = __ldg(&rois[k * 5 + 3]) * 0.0625f;
        float y2 = __ldg(&rois[k * 5 + 4]) * 0.0625f;
        float bh = fmaxf(y2 - y1, 0.0f) * (1.0f / 7.0f);
        float bw = fmaxf(x2 - x1, 0.0f) * (1.0f / 7.0f);
        float xv = x1 + (float)tid * bw;
        float yv = y1 + (float)tid * bh;
        s_vx[tid] = (xv >= 0.0f && xv < (float)WW) ? 1.0f : 0.0f;
        s_vy[tid] = (yv >= 0.0f && yv < (float)HH) ? 1.0f : 0.0f;
        int x0 = (int)floorf(xv);  x0 = min(max(x0, 0), WW - 2);
        int y0 = (int)floorf(yv);  y0 = min(max(y0, 0), HH - 2);
        s_x0[tid] = x0;  s_y0[tid] = y0;
        s_wx[tid] = xv - (float)x0;
        s_wy[tid] = yv - (float)y0;
        if (tid == 0) s_b = (int)__ldg(&rois[k * 5 + 0]);
    }
    __syncthreads();

    if (tid < 64) {
        int gy = tid >> 3, gx = tid & 7;
        float wy = s_wy[gy], wx = s_wx[gx];
        float sc = 0.25f * s_vy[gy] * s_vx[gx];
        s_w[gy][gx][0] = (1.0f - wy) * (1.0f - wx) * sc;
        s_w[gy][gx][1] = (1.0f - wy) * wx * sc;
        s_w[gy][gx][2] = wy * (1.0f - wx) * sc;
        s_w[gy][gx][3] = wy * wx * sc;
    }
    __syncthreads();

    const __half* bptr = FT + (size_t)s_b * (NPIX * CH)
                            + (size_t)chunk * 512 + tid * 2;
    float* outk = out + (size_t)k * (CH * 49) + (size_t)chunk * (512 * 49);

    roi_phase<0, 4>(bptr, outk, tid, s_w, s_x0, s_y0);   // pooled rows 0-3
    roi_phase<4, 3>(bptr, outk, tid, s_w, s_x0, s_y0);   // pooled rows 4-6
}

// ---------------------------------------------------------------------------
extern "C" void kernel_launch(void* const* d_in, const int* in_sizes, int n_in,
                              void* d_out, int out_size) {
    const float* features = (const float*)d_in[0];
    const float* rois     = (const float*)d_in[1];
    float* out            = (float*)d_out;

    const int smem = 512 * SSTR * sizeof(float);   // 59392 B
    cudaFuncSetAttribute(roi_pool_kernel,
                         cudaFuncAttributeMaxDynamicSharedMemorySize, smem);

    dim3 tgrid((NPIX + 127) / 128, CH / 32, BB);   // (20, 32, 4)
    transpose_kernel<<<tgrid, 256>>>(features);
    roi_pool_kernel<<<dim3(KK, 2), 256, smem>>>(rois, out);
}

// round 9
// speedup vs baseline: 1.1492x; 1.0616x over previous
#include <cuda_runtime.h>
#include <cuda_fp16.h>
#include <cstdint>

#define BB 4
#define CH 1024
#define HH 50
#define WW 50
#define KK 512
#define NPIX (HH*WW)              // 2500
#define GPTS 8

#define PF_L1(addr) asm volatile("prefetch.global.L1 [%0];" :: "l"(addr))

// NHWC-transposed features in fp16: [B][H][W][C]  (20.5 MB scratch)
__device__ __align__(16) __half FT[BB * HH * WW * CH];

// ---------------------------------------------------------------------------
// Kernel 1: NCHW fp32 -> NHWC fp16 transpose-convert (measured ~12us)
// ---------------------------------------------------------------------------
__global__ __launch_bounds__(256)
void transpose_kernel(const float* __restrict__ f) {
    __shared__ __align__(16) float tile[32][133];
    const int b  = blockIdx.z;
    const int p0 = blockIdx.x * 128;
    const int c0 = blockIdx.y * 32;
    const int t  = threadIdx.x;

    const float* fb = f + (size_t)b * CH * NPIX + (size_t)c0 * NPIX;
    #pragma unroll
    for (int j = 0; j < 4; j++) {
        int idx = t + j * 256;
        int c = idx >> 5;
        int q = idx & 31;
        int p = p0 + 4 * q;
        float4 v = make_float4(0.f, 0.f, 0.f, 0.f);
        if (p < NPIX) v = *(const float4*)(fb + (size_t)c * NPIX + p);
        tile[c][4 * q + 0] = v.x;
        tile[c][4 * q + 1] = v.y;
        tile[c][4 * q + 2] = v.z;
        tile[c][4 * q + 3] = v.w;
    }
    __syncthreads();

    __half* ob = FT + (size_t)b * NPIX * CH + c0;
    #pragma unroll
    for (int j = 0; j < 2; j++) {
        int idx = t + j * 256;
        int p = idx >> 2;
        int g = idx & 3;
        if (p0 + p < NPIX) {
            __half2 h0 = __floats2half2_rn(tile[8*g + 0][p], tile[8*g + 1][p]);
            __half2 h1 = __floats2half2_rn(tile[8*g + 2][p], tile[8*g + 3][p]);
            __half2 h2 = __floats2half2_rn(tile[8*g + 4][p], tile[8*g + 5][p]);
            __half2 h3 = __floats2half2_rn(tile[8*g + 6][p], tile[8*g + 7][p]);
            uint4 v;
            v.x = *(const unsigned int*)&h0;
            v.y = *(const unsigned int*)&h1;
            v.z = *(const unsigned int*)&h2;
            v.w = *(const unsigned int*)&h3;
            *(uint4*)(ob + (size_t)(p0 + p) * CH + 8 * g) = v;
        }
    }
}

// ---------------------------------------------------------------------------
// Kernel 2: fused RoIAlign (8x8 grid) + 2x2 avg pool -> (K,C,7,7)
// R6 structure (best known): grid (K,2), 256 thr, 2 ch/thread half2 taps,
// 49xfloat2 register accumulator, smem weight table, chunked float4 stores.
// NEW: prefetch.global.L1 of next grid row's taps (no reg/scoreboard cost)
// to convert ~250cyc L2 tap latency into ~39cyc L1 hits.
// ---------------------------------------------------------------------------
__global__ __launch_bounds__(256, 2)
void roi_pool_kernel(const float* __restrict__ rois, float* __restrict__ out) {
    const int k     = blockIdx.x;
    const int chunk = blockIdx.y;          // 0 or 1: channel half
    const int tid   = threadIdx.x;

    __shared__ __align__(16) float sbuf[128 * 49];     // 25 KB staging
    __shared__ __align__(16) float s_w[GPTS][GPTS][4]; // folded weights
    __shared__ float s_wx[GPTS], s_wy[GPTS], s_vx[GPTS], s_vy[GPTS];
    __shared__ int   s_x0[GPTS], s_y0[GPTS];
    __shared__ int   s_b;

    if (tid < GPTS) {
        float x1 = __ldg(&rois[k * 5 + 1]) * 0.0625f;
        float y1 = __ldg(&rois[k * 5 + 2]) * 0.0625f;
        float x2 = __ldg(&rois[k * 5 + 3]) * 0.0625f;
        float y2 = __ldg(&rois[k * 5 + 4]) * 0.0625f;
        float bh = fmaxf(y2 - y1, 0.0f) * (1.0f / 7.0f);
        float bw = fmaxf(x2 - x1, 0.0f) * (1.0f / 7.0f);
        float xv = x1 + (float)tid * bw;
        float yv = y1 + (float)tid * bh;
        s_vx[tid] = (xv >= 0.0f && xv < (float)WW) ? 1.0f : 0.0f;
        s_vy[tid] = (yv >= 0.0f && yv < (float)HH) ? 1.0f : 0.0f;
        int x0 = (int)floorf(xv);  x0 = min(max(x0, 0), WW - 2);
        int y0 = (int)floorf(yv);  y0 = min(max(y0, 0), HH - 2);
        s_x0[tid] = x0;  s_y0[tid] = y0;
        s_wx[tid] = xv - (float)x0;
        s_wy[tid] = yv - (float)y0;
        if (tid == 0) s_b = (int)__ldg(&rois[k * 5 + 0]);
    }
    __syncthreads();

    // per-thread base pointer + hoisted column offsets
    const int c0 = chunk * 512 + tid * 2;
    const __half* bptr = FT + (size_t)s_b * (NPIX * CH) + c0;
    int xoff[GPTS];
    #pragma unroll
    for (int gx = 0; gx < GPTS; gx++) xoff[gx] = s_x0[gx] * CH;

    // warm L1 with grid row 0 while the weight table is being built
    {
        const __half* rp0 = bptr + (size_t)s_y0[0] * (WW * CH);
        #pragma unroll
        for (int gx = 0; gx < GPTS; gx++) {
            const __half* p = rp0 + xoff[gx];
            PF_L1(p);
            PF_L1(p + CH);
            PF_L1(p + WW * CH);
            PF_L1(p + WW * CH + CH);
        }
    }

    // folded bilinear weights (incl. 0.25 pool factor and valid mask)
    if (tid < 64) {
        int gy = tid >> 3, gx = tid & 7;
        float wy = s_wy[gy], wx = s_wx[gx];
        float sc = 0.25f * s_vy[gy] * s_vx[gx];
        s_w[gy][gx][0] = (1.0f - wy) * (1.0f - wx) * sc;
        s_w[gy][gx][1] = (1.0f - wy) * wx * sc;
        s_w[gy][gx][2] = wy * (1.0f - wx) * sc;
        s_w[gy][gx][3] = wy * wx * sc;
    }
    __syncthreads();

    float2 acc[49];
    #pragma unroll
    for (int i = 0; i < 49; i++) { acc[i].x = 0.0f; acc[i].y = 0.0f; }

    #pragma unroll
    for (int gy = 0; gy < GPTS; gy++) {
        const __half* rp = bptr + (size_t)s_y0[gy] * (WW * CH);
        const __half* rpn = (gy < GPTS - 1)
                          ? bptr + (size_t)s_y0[gy + 1] * (WW * CH) : rp;
        #pragma unroll
        for (int gx = 0; gx < GPTS; gx++) {
            const float4 w = *(const float4*)&s_w[gy][gx][0];

            const __half* p = rp + xoff[gx];
            float2 f00 = __half22float2(*(const __half2*)(p));
            float2 f01 = __half22float2(*(const __half2*)(p + CH));
            float2 f10 = __half22float2(*(const __half2*)(p + WW * CH));
            float2 f11 = __half22float2(*(const __half2*)(p + WW * CH + CH));

            // prefetch same-gx taps of the next grid row (L1, no reg cost)
            if (gy < GPTS - 1) {
                const __half* q = rpn + xoff[gx];
                PF_L1(q);
                PF_L1(q + CH);
                PF_L1(q + WW * CH);
                PF_L1(q + WW * CH + CH);
            }

            float ax = f00.x*w.x + f01.x*w.y + f10.x*w.z + f11.x*w.w;
            float ay = f00.y*w.x + f01.y*w.y + f10.y*w.z + f11.y*w.w;

            if (gy >= 1 && gx >= 1) { acc[(gy-1)*7 + (gx-1)].x += ax; acc[(gy-1)*7 + (gx-1)].y += ay; }
            if (gy >= 1 && gx <  7) { acc[(gy-1)*7 +  gx   ].x += ax; acc[(gy-1)*7 +  gx   ].y += ay; }
            if (gy <  7 && gx >= 1) { acc[ gy   *7 + (gx-1)].x += ax; acc[ gy   *7 + (gx-1)].y += ay; }
            if (gy <  7 && gx <  7) { acc[ gy   *7 +  gx   ].x += ax; acc[ gy   *7 +  gx   ].y += ay; }
        }
    }

    // ---- staged, coalesced output writes (unchanged, load-bearing) -----
    float* outk = out + (size_t)k * (CH * 49) + (size_t)chunk * (512 * 49);
    #pragma unroll
    for (int sub = 0; sub < 4; sub++) {
        if ((tid >> 6) == sub) {
            int cl = tid * 2 - sub * 128;   // 0..126, even
            #pragma unroll
            for (int i = 0; i < 49; i++) {
                sbuf[(cl    ) * 49 + i] = acc[i].x;
                sbuf[(cl + 1) * 49 + i] = acc[i].y;
            }
        }
        __syncthreads();
        const float4* s4 = (const float4*)sbuf;
        float4* o4 = (float4*)(outk + sub * 6272);
        #pragma unroll
        for (int j = 0; j < 7; j++) {
            int i = tid + j * 256;
            if (i < 1568) o4[i] = s4[i];
        }
        __syncthreads();
    }
}

// ---------------------------------------------------------------------------
extern "C" void kernel_launch(void* const* d_in, const int* in_sizes, int n_in,
                              void* d_out, int out_size) {
    const float* features = (const float*)d_in[0];
    const float* rois     = (const float*)d_in[1];
    float* out            = (float*)d_out;

    dim3 tgrid((NPIX + 127) / 128, CH / 32, BB);   // (20, 32, 4)
    transpose_kernel<<<tgrid, 256>>>(features);
    roi_pool_kernel<<<dim3(KK, 2), 256>>>(rois, out);
}

// round 10
// speedup vs baseline: 1.3342x; 1.1610x over previous
#include <cuda_runtime.h>
#include <cuda_fp16.h>
#include <cstdint>

#define BB 4
#define CH 1024
#define HH 50
#define WW 50
#define KK 512
#define NPIX (HH*WW)              // 2500
#define GPTS 8

// NHWC-transposed features in fp16: [B][H][W][C]  (20.5 MB scratch)
__device__ __align__(16) __half FT[BB * HH * WW * CH];

__device__ __forceinline__ uint32_t smem_u32(const void* p) {
    uint32_t a;
    asm("{ .reg .u64 t; cvta.to.shared.u64 t, %1; cvt.u32.u64 %0, t; }"
        : "=r"(a) : "l"(p));
    return a;
}
#define CP_ASYNC16(s, g) \
    asm volatile("cp.async.ca.shared.global [%0], [%1], 16;" :: "r"(s), "l"(g))
template<int N> __device__ __forceinline__ void cp_wait() {
    asm volatile("cp.async.wait_group %0;" :: "n"(N));
}
__device__ __forceinline__ void cp_commit() {
    asm volatile("cp.async.commit_group;");
}

// ---------------------------------------------------------------------------
// Kernel 1: NCHW fp32 -> NHWC fp16 transpose-convert (measured ~12us)
// ---------------------------------------------------------------------------
__global__ __launch_bounds__(256)
void transpose_kernel(const float* __restrict__ f) {
    __shared__ __align__(16) float tile[32][133];
    const int b  = blockIdx.z;
    const int p0 = blockIdx.x * 128;
    const int c0 = blockIdx.y * 32;
    const int t  = threadIdx.x;

    const float* fb = f + (size_t)b * CH * NPIX + (size_t)c0 * NPIX;
    #pragma unroll
    for (int j = 0; j < 4; j++) {
        int idx = t + j * 256;
        int c = idx >> 5;
        int q = idx & 31;
        int p = p0 + 4 * q;
        float4 v = make_float4(0.f, 0.f, 0.f, 0.f);
        if (p < NPIX) v = *(const float4*)(fb + (size_t)c * NPIX + p);
        tile[c][4 * q + 0] = v.x;
        tile[c][4 * q + 1] = v.y;
        tile[c][4 * q + 2] = v.z;
        tile[c][4 * q + 3] = v.w;
    }
    __syncthreads();

    __half* ob = FT + (size_t)b * NPIX * CH + c0;
    #pragma unroll
    for (int j = 0; j < 2; j++) {
        int idx = t + j * 256;
        int p = idx >> 2;
        int g = idx & 3;
        if (p0 + p < NPIX) {
            __half2 h0 = __floats2half2_rn(tile[8*g + 0][p], tile[8*g + 1][p]);
            __half2 h1 = __floats2half2_rn(tile[8*g + 2][p], tile[8*g + 3][p]);
            __half2 h2 = __floats2half2_rn(tile[8*g + 4][p], tile[8*g + 5][p]);
            __half2 h3 = __floats2half2_rn(tile[8*g + 6][p], tile[8*g + 7][p]);
            uint4 v;
            v.x = *(const unsigned int*)&h0;
            v.y = *(const unsigned int*)&h1;
            v.z = *(const unsigned int*)&h2;
            v.w = *(const unsigned int*)&h3;
            *(uint4*)(ob + (size_t)(p0 + p) * CH + 8 * g) = v;
        }
    }
}

// ---------------------------------------------------------------------------
// Kernel 2: fused RoIAlign + 2x2 avg pool, cp.async double-buffered taps.
// Grid (K,2): 512 channels/CTA, 256 threads, 2 ch/thread.
// Per grid row gy: 32 tap segments (8 gx x 4 taps) x 1KB -> smem via
// cp.async (8x16B per thread), double-buffered; compute reads taps from
// smem (LDS.32). 49xfloat2 register accumulator + R6's float4 drain
// (staging aliases gather buffer 0).
// ---------------------------------------------------------------------------
#define TB_BYTES 32768            // one tap buffer: 32 segs x 1KB

extern __shared__ __align__(16) unsigned char dynsmem[];   // 2*TB_BYTES

__global__ __launch_bounds__(256, 2)
void roi_pool_kernel(const float* __restrict__ rois, float* __restrict__ out) {
    const int k     = blockIdx.x;
    const int chunk = blockIdx.y;          // channel half
    const int tid   = threadIdx.x;

    __shared__ __align__(16) float s_w[GPTS][GPTS][4];
    __shared__ float s_wx[GPTS], s_wy[GPTS], s_vx[GPTS], s_vy[GPTS];
    __shared__ int   s_x0[GPTS], s_y0[GPTS];
    __shared__ int   s_b;

    if (tid < GPTS) {
        float x1 = __ldg(&rois[k * 5 + 1]) * 0.0625f;
        float y1 = __ldg(&rois[k * 5 + 2]) * 0.0625f;
        float x2 = __ldg(&rois[k * 5 + 3]) * 0.0625f;
        float y2 = __ldg(&rois[k * 5 + 4]) * 0.0625f;
        float bh = fmaxf(y2 - y1, 0.0f) * (1.0f / 7.0f);
        float bw = fmaxf(x2 - x1, 0.0f) * (1.0f / 7.0f);
        float xv = x1 + (float)tid * bw;
        float yv = y1 + (float)tid * bh;
        s_vx[tid] = (xv >= 0.0f && xv < (float)WW) ? 1.0f : 0.0f;
        s_vy[tid] = (yv >= 0.0f && yv < (float)HH) ? 1.0f : 0.0f;
        int x0 = (int)floorf(xv);  x0 = min(max(x0, 0), WW - 2);
        int y0 = (int)floorf(yv);  y0 = min(max(y0, 0), HH - 2);
        s_x0[tid] = x0;  s_y0[tid] = y0;
        s_wx[tid] = xv - (float)x0;
        s_wy[tid] = yv - (float)y0;
        if (tid == 0) s_b = (int)__ldg(&rois[k * 5 + 0]);
    }
    __syncthreads();

    if (tid < 64) {
        int gy = tid >> 3, gx = tid & 7;
        float wy = s_wy[gy], wx = s_wx[gx];
        float sc = 0.25f * s_vy[gy] * s_vx[gx];
        s_w[gy][gx][0] = (1.0f - wy) * (1.0f - wx) * sc;
        s_w[gy][gx][1] = (1.0f - wy) * wx * sc;
        s_w[gy][gx][2] = wy * (1.0f - wx) * sc;
        s_w[gy][gx][3] = wy * wx * sc;
    }

    // per-thread gather role: t4 = tap index, col = 16B chunk in segment
    const int t4  = tid >> 6;              // 0..3 -> (dy,dx)
    const int dy  = t4 >> 1, dx = t4 & 1;
    const int col = tid & 63;
    const __half* bbase = FT + (size_t)s_b * (NPIX * CH) + chunk * 512
                             + (size_t)dx * CH + col * 8;
    int xoff[GPTS];
    #pragma unroll
    for (int gx = 0; gx < GPTS; gx++) xoff[gx] = s_x0[gx] * CH;

    const uint32_t tb0 = smem_u32(dynsmem);
    const uint32_t smy = tb0 + (t4 * 1024 + col * 16);   // seg t4 base + chunk

    // gather grid row gy into buffer bi (8 x cp.async per thread)
    #define GATHER(gy, bi)                                                  \
        do {                                                                \
            const __half* rb = bbase + (size_t)(s_y0[gy] + dy) * (WW * CH); \
            uint32_t sb = smy + (bi) * TB_BYTES;                            \
            _Pragma("unroll")                                               \
            for (int j = 0; j < 8; j++)                                     \
                CP_ASYNC16(sb + j * 4096, rb + xoff[j]);                    \
            cp_commit();                                                    \
        } while (0)

    GATHER(0, 0);                          // prologue

    float2 acc[49];
    #pragma unroll
    for (int i = 0; i < 49; i++) { acc[i].x = 0.0f; acc[i].y = 0.0f; }

    #pragma unroll
    for (int gy = 0; gy < GPTS; gy++) {
        if (gy < GPTS - 1) GATHER(gy + 1, (gy + 1) & 1);
        if (gy < GPTS - 1) cp_wait<1>(); else cp_wait<0>();
        __syncthreads();                   // all threads' row-gy taps visible

        const unsigned char* buf = dynsmem + (gy & 1) * TB_BYTES;
        #pragma unroll
        for (int gx = 0; gx < GPTS; gx++) {
            const float4 w = *(const float4*)&s_w[gy][gx][0];
            const unsigned char* sp = buf + (gx * 4) * 1024 + tid * 4;
            float2 f00 = __half22float2(*(const __half2*)(sp));
            float2 f01 = __half22float2(*(const __half2*)(sp + 1024));
            float2 f10 = __half22float2(*(const __half2*)(sp + 2048));
            float2 f11 = __half22float2(*(const __half2*)(sp + 3072));

            float ax = f00.x*w.x + f01.x*w.y + f10.x*w.z + f11.x*w.w;
            float ay = f00.y*w.x + f01.y*w.y + f10.y*w.z + f11.y*w.w;

            if (gy >= 1 && gx >= 1) { acc[(gy-1)*7 + (gx-1)].x += ax; acc[(gy-1)*7 + (gx-1)].y += ay; }
            if (gy >= 1 && gx <  7) { acc[(gy-1)*7 +  gx   ].x += ax; acc[(gy-1)*7 +  gx   ].y += ay; }
            if (gy <  7 && gx >= 1) { acc[ gy   *7 + (gx-1)].x += ax; acc[ gy   *7 + (gx-1)].y += ay; }
            if (gy <  7 && gx <  7) { acc[ gy   *7 +  gx   ].x += ax; acc[ gy   *7 +  gx   ].y += ay; }
        }
        __syncthreads();                   // done reading buf before reuse
    }

    // ---- staged, coalesced output writes (staging aliases buffer 0) ----
    float* sbuf = (float*)dynsmem;         // 25088 B < TB_BYTES
    float* outk = out + (size_t)k * (CH * 49) + (size_t)chunk * (512 * 49);
    #pragma unroll
    for (int sub = 0; sub < 4; sub++) {
        if ((tid >> 6) == sub) {
            int cl = tid * 2 - sub * 128;
            #pragma unroll
            for (int i = 0; i < 49; i++) {
                sbuf[(cl    ) * 49 + i] = acc[i].x;
                sbuf[(cl + 1) * 49 + i] = acc[i].y;
            }
        }
        __syncthreads();
        const float4* s4 = (const float4*)sbuf;
        float4* o4 = (float4*)(outk + sub * 6272);
        #pragma unroll
        for (int j = 0; j < 7; j++) {
            int i = tid + j * 256;
            if (i < 1568) o4[i] = s4[i];
        }
        __syncthreads();
    }
}

// ---------------------------------------------------------------------------
extern "C" void kernel_launch(void* const* d_in, const int* in_sizes, int n_in,
                              void* d_out, int out_size) {
    const float* features = (const float*)d_in[0];
    const float* rois     = (const float*)d_in[1];
    float* out            = (float*)d_out;

    const int smem = 2 * TB_BYTES;         // 64 KB
    static int done = 0;
    if (!done) {
        cudaFuncSetAttribute(roi_pool_kernel,
                             cudaFuncAttributeMaxDynamicSharedMemorySize, smem);
        done = 1;
    }

    dim3 tgrid((NPIX + 127) / 128, CH / 32, BB);   // (20, 32, 4)
    transpose_kernel<<<tgrid, 256>>>(features);
    roi_pool_kernel<<<dim3(KK, 2), 256, smem>>>(rois, out);
}